// round 7
// baseline (speedup 1.0000x reference)
#include <cuda_runtime.h>
#include <cuda_bf16.h>
#include <cstdint>
#include <math.h>

#define NROWS 102400      // BS * N_AGENTS
#define NBATCH 2048
#define QSIZE (NROWS * 8)

// ---------------- static scratch ----------------
// Split layout: row-major [rows][256] bf16, cols 0..127 = hi, 128..255 = lo.
__device__ __nv_bfloat16  g_xs[NROWS * 256];     // GCN activations, split
__device__ float          g_bufY[NROWS * 128];   // GCN gemm output (fp32)
__device__ float          g_gi[NROWS * 384];
__device__ __nv_bfloat16  g_wgs[128 * 256];      // w_gcn split
__device__ __nv_bfloat16  g_wihs[384 * 256];     // w_ih split
__device__ __nv_bfloat16  g_whhs[384 * 256];     // w_hh split

// smem tile geometry: K=256 ([hi|lo]) + 8 pad; 3 segment passes emulate K=384
#define LDS_K 264
#define TILE_BF16 (128 * LDS_K)          // 33792 elems = 67584 B
#define GEMM_SMEM (2 * TILE_BF16 * 2)                    // 135168 B
#define RBUF_LD 132
#define GRU_SMEM (2 * TILE_BF16 * 2 + 128 * RBUF_LD * 4) // 202752 B

// ---------------------------------------------------------------------------
// shared device helpers
// ---------------------------------------------------------------------------
// Fill a [128][LDS_K] smem tile from a [rows][256] bf16 (hi|lo) source.
__device__ __forceinline__ void fill_bf16(__nv_bfloat16* S, const __nv_bfloat16* G,
                                          int tid) {
    const uint4* g = reinterpret_cast<const uint4*>(G);   // 32 uint4 per row
    for (int i = tid; i < 128 * 32; i += 256) {
        int r = i >> 5, c = i & 31;
        *reinterpret_cast<uint4*>(&S[r * LDS_K + c * 8]) = g[r * 32 + c];
    }
}
// Fill [128][LDS_K] smem tile from fp32 [rows][128], splitting hi|lo on the fly.
__device__ __forceinline__ void fill_f32split(__nv_bfloat16* S, const float* G,
                                              int tid) {
    const float4* g = reinterpret_cast<const float4*>(G);  // 32 float4 per row
    for (int i = tid; i < 128 * 32; i += 256) {
        int r = i >> 5, c = i & 31;
        float4 v = g[r * 32 + c];
        __nv_bfloat16 h0 = __float2bfloat16(v.x), h1 = __float2bfloat16(v.y);
        __nv_bfloat16 h2 = __float2bfloat16(v.z), h3 = __float2bfloat16(v.w);
        __nv_bfloat162 H0{h0, h1}, H1{h2, h3};
        __nv_bfloat162 L0{__float2bfloat16(v.x - __bfloat162float(h0)),
                          __float2bfloat16(v.y - __bfloat162float(h1))};
        __nv_bfloat162 L1{__float2bfloat16(v.z - __bfloat162float(h2)),
                          __float2bfloat16(v.w - __bfloat162float(h3))};
        __nv_bfloat16* hp = &S[r * LDS_K + c * 4];
        __nv_bfloat16* lp = &S[r * LDS_K + 128 + c * 4];
        *reinterpret_cast<__nv_bfloat162*>(hp)     = H0;
        *reinterpret_cast<__nv_bfloat162*>(hp + 2) = H1;
        *reinterpret_cast<__nv_bfloat162*>(lp)     = L0;
        *reinterpret_cast<__nv_bfloat162*>(lp + 2) = L1;
    }
}
// Compensated K=384 MMA over [hi|lo] tiles: segments (A,B) offsets
// (0,0)=hi*hi, (128,0)=lo*hi, (0,128)=hi*lo.
__device__ __forceinline__ void mma_comp(const __nv_bfloat16* As, const __nv_bfloat16* Bs,
                                         int mrow0, int ncol0, int grp, int tig,
                                         float (&acc)[2][8][4]) {
#pragma unroll
    for (int mt = 0; mt < 2; mt++)
#pragma unroll
        for (int nt = 0; nt < 8; nt++)
#pragma unroll
            for (int q = 0; q < 4; q++) acc[mt][nt][q] = 0.f;

    const int segA[3] = {0, 128, 0};
    const int segB[3] = {0, 0, 128};
#pragma unroll
    for (int seg = 0; seg < 3; seg++) {
#pragma unroll
        for (int ks = 0; ks < 8; ks++) {
            int ka = segA[seg] + ks * 16;
            int kb = segB[seg] + ks * 16;
            uint32_t afr[2][4];
#pragma unroll
            for (int mt = 0; mt < 2; mt++) {
                int r = mrow0 + mt * 16 + grp;
                const uint32_t* p0 = reinterpret_cast<const uint32_t*>(&As[r * LDS_K + ka + tig * 2]);
                const uint32_t* p1 = reinterpret_cast<const uint32_t*>(&As[(r + 8) * LDS_K + ka + tig * 2]);
                afr[mt][0] = p0[0];
                afr[mt][1] = p1[0];
                afr[mt][2] = p0[4];
                afr[mt][3] = p1[4];
            }
            uint32_t bfr[8][2];
#pragma unroll
            for (int nt = 0; nt < 8; nt++) {
                int n = ncol0 + nt * 8 + grp;
                const uint32_t* q = reinterpret_cast<const uint32_t*>(&Bs[n * LDS_K + kb + tig * 2]);
                bfr[nt][0] = q[0];
                bfr[nt][1] = q[4];
            }
#pragma unroll
            for (int mt = 0; mt < 2; mt++)
#pragma unroll
                for (int nt = 0; nt < 8; nt++)
                    asm volatile(
                        "mma.sync.aligned.m16n8k16.row.col.f32.bf16.bf16.f32 "
                        "{%0,%1,%2,%3}, {%4,%5,%6,%7}, {%8,%9}, {%0,%1,%2,%3};"
                        : "+f"(acc[mt][nt][0]), "+f"(acc[mt][nt][1]),
                          "+f"(acc[mt][nt][2]), "+f"(acc[mt][nt][3])
                        : "r"(afr[mt][0]), "r"(afr[mt][1]), "r"(afr[mt][2]), "r"(afr[mt][3]),
                          "r"(bfr[nt][0]), "r"(bfr[nt][1]));
        }
    }
}

// ---------------------------------------------------------------------------
// GEMM: C[M x (nchunks*128)] = A @ W^T (+bias). A either split-bf16 or fp32.
// ---------------------------------------------------------------------------
template <bool F32A>
__global__ void __launch_bounds__(256)
gemm_k(const void* __restrict__ Ap, const __nv_bfloat16* __restrict__ W,
       const float* __restrict__ bias, float* __restrict__ out, int ldc, int nchunks) {
    extern __shared__ __nv_bfloat16 sm[];
    __nv_bfloat16* As = sm;
    __nv_bfloat16* Bs = sm + TILE_BF16;

    int tid = threadIdx.x;
    int wid = tid >> 5, lane = tid & 31;
    int grp = lane >> 2, tig = lane & 3;
    int mrow0 = (wid & 3) * 32;
    int ncol0 = (wid >> 2) * 64;
    size_t m0 = (size_t)blockIdx.x * 128;

    if (F32A)
        fill_f32split(As, reinterpret_cast<const float*>(Ap) + m0 * 128, tid);
    else
        fill_bf16(As, reinterpret_cast<const __nv_bfloat16*>(Ap) + m0 * 256, tid);

    for (int j = 0; j < nchunks; j++) {
        fill_bf16(Bs, W + (size_t)j * 128 * 256, tid);
        __syncthreads();

        float acc[2][8][4];
        mma_comp(As, Bs, mrow0, ncol0, grp, tig, acc);

        int cbase = j * 128;
#pragma unroll
        for (int mt = 0; mt < 2; mt++) {
#pragma unroll
            for (int nt = 0; nt < 8; nt++) {
                size_t row = m0 + mrow0 + mt * 16 + grp;
                int col = cbase + ncol0 + nt * 8 + tig * 2;
                float b0 = 0.f, b1 = 0.f;
                if (bias) { b0 = bias[col]; b1 = bias[col + 1]; }
                float2 v0 = {acc[mt][nt][0] + b0, acc[mt][nt][1] + b1};
                float2 v1 = {acc[mt][nt][2] + b0, acc[mt][nt][3] + b1};
                *reinterpret_cast<float2*>(&out[row * ldc + col]) = v0;
                *reinterpret_cast<float2*>(&out[(row + 8) * ldc + col]) = v1;
            }
        }
        __syncthreads();
    }
}

// ---------------------------------------------------------------------------
// Fused gh GEMM + GRU gates. A = hidden (fp32, split on the fly), W = w_hh split.
// chunk0 -> r (smem), chunk1 -> z (regs), chunk2 -> n, finalize h.
// gi (incl. b_ih) read from global; h = (1-z)*n + z*h_in.
// ---------------------------------------------------------------------------
__global__ void __launch_bounds__(256)
gemm_gru(const float* __restrict__ hidden, const __nv_bfloat16* __restrict__ W,
         const float* __restrict__ gi, const float* __restrict__ b_hh,
         float* __restrict__ h_out) {
    extern __shared__ __nv_bfloat16 sm[];
    __nv_bfloat16* As = sm;
    __nv_bfloat16* Bs = sm + TILE_BF16;
    float* rbuf = reinterpret_cast<float*>(sm + 2 * TILE_BF16);  // [128][RBUF_LD]

    int tid = threadIdx.x;
    int wid = tid >> 5, lane = tid & 31;
    int grp = lane >> 2, tig = lane & 3;
    int mrow0 = (wid & 3) * 32;
    int ncol0 = (wid >> 2) * 64;
    size_t m0 = (size_t)blockIdx.x * 128;

    fill_f32split(As, hidden + m0 * 128, tid);

    float zreg[2][8][4];

    for (int j = 0; j < 3; j++) {
        fill_bf16(Bs, W + (size_t)j * 128 * 256, tid);
        __syncthreads();

        float acc[2][8][4];
        mma_comp(As, Bs, mrow0, ncol0, grp, tig, acc);

#pragma unroll
        for (int mt = 0; mt < 2; mt++) {
#pragma unroll
            for (int nt = 0; nt < 8; nt++) {
                int rl0 = mrow0 + mt * 16 + grp;           // local row (and +8)
                size_t row0 = m0 + rl0;
                int c = ncol0 + nt * 8 + tig * 2;          // hidden dim 0..127
                float bb0 = b_hh[j * 128 + c], bb1 = b_hh[j * 128 + c + 1];
                float2 gi0 = *reinterpret_cast<const float2*>(&gi[row0 * 384 + j * 128 + c]);
                float2 gi1 = *reinterpret_cast<const float2*>(&gi[(row0 + 8) * 384 + j * 128 + c]);
                float gh00 = acc[mt][nt][0] + bb0, gh01 = acc[mt][nt][1] + bb1;
                float gh10 = acc[mt][nt][2] + bb0, gh11 = acc[mt][nt][3] + bb1;
                if (j == 0) {            // r gate -> smem
                    rbuf[rl0 * RBUF_LD + c]           = 1.f / (1.f + expf(-(gi0.x + gh00)));
                    rbuf[rl0 * RBUF_LD + c + 1]       = 1.f / (1.f + expf(-(gi0.y + gh01)));
                    rbuf[(rl0 + 8) * RBUF_LD + c]     = 1.f / (1.f + expf(-(gi1.x + gh10)));
                    rbuf[(rl0 + 8) * RBUF_LD + c + 1] = 1.f / (1.f + expf(-(gi1.y + gh11)));
                } else if (j == 1) {     // z gate -> regs
                    zreg[mt][nt][0] = 1.f / (1.f + expf(-(gi0.x + gh00)));
                    zreg[mt][nt][1] = 1.f / (1.f + expf(-(gi0.y + gh01)));
                    zreg[mt][nt][2] = 1.f / (1.f + expf(-(gi1.x + gh10)));
                    zreg[mt][nt][3] = 1.f / (1.f + expf(-(gi1.y + gh11)));
                } else {                 // n gate + finalize
                    float r00 = rbuf[rl0 * RBUF_LD + c];
                    float r01 = rbuf[rl0 * RBUF_LD + c + 1];
                    float r10 = rbuf[(rl0 + 8) * RBUF_LD + c];
                    float r11 = rbuf[(rl0 + 8) * RBUF_LD + c + 1];
                    float n00 = tanhf(gi0.x + r00 * gh00);
                    float n01 = tanhf(gi0.y + r01 * gh01);
                    float n10 = tanhf(gi1.x + r10 * gh10);
                    float n11 = tanhf(gi1.y + r11 * gh11);
                    float2 hv0 = *reinterpret_cast<const float2*>(&hidden[row0 * 128 + c]);
                    float2 hv1 = *reinterpret_cast<const float2*>(&hidden[(row0 + 8) * 128 + c]);
                    float z00 = zreg[mt][nt][0], z01 = zreg[mt][nt][1];
                    float z10 = zreg[mt][nt][2], z11 = zreg[mt][nt][3];
                    float2 o0 = {(1.f - z00) * n00 + z00 * hv0.x,
                                 (1.f - z01) * n01 + z01 * hv0.y};
                    float2 o1 = {(1.f - z10) * n10 + z10 * hv1.x,
                                 (1.f - z11) * n11 + z11 * hv1.y};
                    *reinterpret_cast<float2*>(&h_out[row0 * 128 + c]) = o0;
                    *reinterpret_cast<float2*>(&h_out[(row0 + 8) * 128 + c]) = o1;
                }
            }
        }
        __syncthreads();
    }
}

// ---------------------------------------------------------------------------
// Per-sample: X = relu(normAdj(50x50) @ Y_b(50x128) + b), fused hi|lo split out.
// ---------------------------------------------------------------------------
__global__ void adj_relu_cvt(const float* __restrict__ Y, const float* __restrict__ adj,
                             const float* __restrict__ bias,
                             __nv_bfloat16* __restrict__ outS) {
    __shared__ float A_s[52][52];
    __shared__ float Yb[52][128];
    int b = blockIdx.x, tid = threadIdx.x;

    for (int i = tid; i < 52 * 52; i += 512) {
        int r = i / 52, c = i - r * 52;
        A_s[r][c] = (r < 50 && c < 50) ? adj[r * 50 + c] : 0.f;
    }
    const float* Yg = Y + (size_t)b * 6400;
    for (int i = tid; i < 52 * 128; i += 512) {
        int r = i >> 7, c = i & 127;
        Yb[r][c] = (r < 50) ? Yg[r * 128 + c] : 0.f;
    }
    __syncthreads();

    int g = tid >> 7, d = tid & 127;
    int i0 = g * 13;
    float acc[13];
#pragma unroll
    for (int i = 0; i < 13; i++) acc[i] = 0.f;

#pragma unroll 1
    for (int j = 0; j < 52; j += 4) {
        float y0 = Yb[j + 0][d], y1 = Yb[j + 1][d];
        float y2 = Yb[j + 2][d], y3 = Yb[j + 3][d];
#pragma unroll
        for (int i = 0; i < 13; i++) {
            float4 a = *reinterpret_cast<const float4*>(&A_s[i0 + i][j]);
            acc[i] += a.x * y0 + a.y * y1 + a.z * y2 + a.w * y3;
        }
    }

    float bv = bias[d];
    __nv_bfloat16* os = outS + (size_t)b * 50 * 256;
#pragma unroll
    for (int i = 0; i < 13; i++) {
        int row = i0 + i;
        if (row < 50) {
            float v = fmaxf(acc[i] + bv, 0.f);
            __nv_bfloat16 h = __float2bfloat16(v);
            os[row * 256 + d]       = h;
            os[row * 256 + 128 + d] = __float2bfloat16(v - __bfloat162float(h));
        }
    }
}

// ---------------------------------------------------------------------------
// fp32 [rows][128] -> bf16 [rows][256] (hi|lo), for weights.
// ---------------------------------------------------------------------------
__global__ void cvt_split(const float* __restrict__ in, __nv_bfloat16* __restrict__ outS,
                          int n4) {
    int i = blockIdx.x * blockDim.x + threadIdx.x;
    if (i >= n4) return;
    float4 v = reinterpret_cast<const float4*>(in)[i];
    int row = i >> 5, c4 = (i & 31) << 2;
    __nv_bfloat16 h0 = __float2bfloat16(v.x), h1 = __float2bfloat16(v.y);
    __nv_bfloat16 h2 = __float2bfloat16(v.z), h3 = __float2bfloat16(v.w);
    __nv_bfloat162 H0{h0, h1}, H1{h2, h3};
    __nv_bfloat162 L0{__float2bfloat16(v.x - __bfloat162float(h0)),
                      __float2bfloat16(v.y - __bfloat162float(h1))};
    __nv_bfloat162 L1{__float2bfloat16(v.z - __bfloat162float(h2)),
                      __float2bfloat16(v.w - __bfloat162float(h3))};
    __nv_bfloat16* base = outS + (size_t)row * 256;
    *reinterpret_cast<__nv_bfloat162*>(base + c4)           = H0;
    *reinterpret_cast<__nv_bfloat162*>(base + c4 + 2)       = H1;
    *reinterpret_cast<__nv_bfloat162*>(base + 128 + c4)     = L0;
    *reinterpret_cast<__nv_bfloat162*>(base + 128 + c4 + 2) = L1;
}

// ---------------------------------------------------------------------------
// q[Mx8] = H[Mx128] @ Wfc2[8x128]^T + b[8]
// ---------------------------------------------------------------------------
__global__ void fc2_kernel(const float* __restrict__ H, const float* __restrict__ W,
                           const float* __restrict__ bias, float* __restrict__ Q) {
    __shared__ float Hs[32][132];
    __shared__ float Ws[8][132];
    int tid = threadIdx.x;
    size_t r0 = (size_t)blockIdx.x * 32;

    for (int i = tid; i < 32 * 32; i += 256) {
        int r = i >> 5, c4 = (i & 31) << 2;
        *(float4*)&Hs[r][c4] = *(const float4*)&H[(r0 + r) * 128 + c4];
    }
    for (int i = tid; i < 8 * 32; i += 256) {
        int r = i >> 5, c4 = (i & 31) << 2;
        *(float4*)&Ws[r][c4] = *(const float4*)&W[r * 128 + c4];
    }
    __syncthreads();

    int rl = tid >> 3, a = tid & 7;
    float acc = 0.f;
#pragma unroll
    for (int k = 0; k < 128; k++) acc += Hs[rl][k] * Ws[a][k];
    Q[(r0 + rl) * 8 + a] = acc + bias[a];
}

// ---------------------------------------------------------------------------
extern "C" void kernel_launch(void* const* d_in, const int* in_sizes, int n_in,
                              void* d_out, int out_size) {
    const float* inputs   = (const float*)d_in[0];
    const float* hidden   = (const float*)d_in[1];
    const float* norm_adj = (const float*)d_in[2];
    const float* w_gcn    = (const float*)d_in[3];
    const float* b_gcn    = (const float*)d_in[4];
    const float* w_ih     = (const float*)d_in[5];
    const float* b_ih     = (const float*)d_in[6];
    const float* w_hh     = (const float*)d_in[7];
    const float* b_hh     = (const float*)d_in[8];
    const float* w_fc2    = (const float*)d_in[9];
    const float* b_fc2    = (const float*)d_in[10];

    float* out = (float*)d_out;
    float* q_out = out;               // (102400, 8)
    float* h_out = out + QSIZE;       // (102400, 128)

    float *bufY, *gi;
    __nv_bfloat16 *xs, *wgs, *wihs, *whhs;
    cudaGetSymbolAddress((void**)&bufY, g_bufY);
    cudaGetSymbolAddress((void**)&gi, g_gi);
    cudaGetSymbolAddress((void**)&xs, g_xs);
    cudaGetSymbolAddress((void**)&wgs, g_wgs);
    cudaGetSymbolAddress((void**)&wihs, g_wihs);
    cudaGetSymbolAddress((void**)&whhs, g_whhs);

    cudaFuncSetAttribute(gemm_k<true>,  cudaFuncAttributeMaxDynamicSharedMemorySize, GEMM_SMEM);
    cudaFuncSetAttribute(gemm_k<false>, cudaFuncAttributeMaxDynamicSharedMemorySize, GEMM_SMEM);
    cudaFuncSetAttribute(gemm_gru,      cudaFuncAttributeMaxDynamicSharedMemorySize, GRU_SMEM);

    // weight conversions (small)
    cvt_split<<<16, 256>>>(w_gcn, wgs, 128 * 128 / 4);
    cvt_split<<<48, 256>>>(w_ih, wihs, 384 * 128 / 4);
    cvt_split<<<48, 256>>>(w_hh, whhs, 384 * 128 / 4);

    const int MT = NROWS / 128;   // 800 row tiles

    // GCN pass 1: fp32 input, split fused into A fill
    gemm_k<true><<<MT, 256, GEMM_SMEM>>>(inputs, wgs, nullptr, bufY, 128, 1);
    adj_relu_cvt<<<NBATCH, 512>>>(bufY, norm_adj, b_gcn, xs);
    // GCN passes 2,3
    for (int p = 1; p < 3; p++) {
        gemm_k<false><<<MT, 256, GEMM_SMEM>>>(xs, wgs, nullptr, bufY, 128, 1);
        adj_relu_cvt<<<NBATCH, 512>>>(bufY, norm_adj, b_gcn, xs);
    }

    // gi = x_c @ w_ih^T + b_ih
    gemm_k<false><<<MT, 256, GEMM_SMEM>>>(xs, wihs, b_ih, gi, 384, 3);
    // gh gemm fused with GRU gates -> h_out
    gemm_gru<<<MT, 256, GRU_SMEM>>>(hidden, whhs, gi, b_hh, h_out);

    // fc2 -> q
    fc2_kernel<<<NROWS / 32, 256>>>(h_out, w_fc2, b_fc2, q_out);
}

// round 8
// speedup vs baseline: 1.1633x; 1.1633x over previous
#include <cuda_runtime.h>
#include <cuda_bf16.h>
#include <cstdint>
#include <math.h>

#define NROWS 102400      // BS * N_AGENTS
#define NBATCH 2048
#define QSIZE (NROWS * 8)

// ---------------- static scratch ----------------
// Split layout: row-major [rows][256] bf16, cols 0..127 = hi, 128..255 = lo.
__device__ __nv_bfloat16  g_xs[NROWS * 256];     // GCN activations, split
__device__ float          g_bufY[NROWS * 128];   // GCN gemm output (fp32)
__device__ float          g_gi[NROWS * 384];
__device__ __nv_bfloat16  g_wgs[128 * 256];      // w_gcn split
__device__ __nv_bfloat16  g_wihs[384 * 256];     // w_ih split
__device__ __nv_bfloat16  g_whhs[384 * 256];     // w_hh split

// smem tile geometry: K=256 ([hi|lo]) + 8 pad; 3 segment passes emulate K=384
#define LDS_K 264
#define BM 64
#define A_TILE (BM * LDS_K)               // bf16 elems
#define B_TILE (128 * LDS_K)
#define GEMM_SMEM ((A_TILE + B_TILE) * 2) // 101376 B

// ---------------- cp.async helpers ----------------
__device__ __forceinline__ uint32_t smem_u32(const void* p) {
    uint32_t a;
    asm("{ .reg .u64 t; cvta.to.shared.u64 t, %1; cvt.u32.u64 %0, t; }" : "=r"(a) : "l"(p));
    return a;
}
#define CP16(dst_u32, src_ptr) \
    asm volatile("cp.async.cg.shared.global [%0], [%1], 16;" :: "r"(dst_u32), "l"(src_ptr))
#define CP_COMMIT()  asm volatile("cp.async.commit_group;" ::: "memory")
#define CP_WAIT0()   asm volatile("cp.async.wait_group 0;" ::: "memory")

// Fill [rows][LDS_K] smem tile from [rows][256] bf16 (hi|lo) via cp.async.
template <int ROWS>
__device__ __forceinline__ void fill_bf16_ca(__nv_bfloat16* S, const __nv_bfloat16* G,
                                             int tid) {
    uint32_t sb = smem_u32(S);
    const uint4* g = reinterpret_cast<const uint4*>(G);
    for (int i = tid; i < ROWS * 32; i += 256) {
        int r = i >> 5, c = i & 31;
        CP16(sb + (r * LDS_K + c * 8) * 2, g + r * 32 + c);
    }
}
// Fill [BM][LDS_K] smem from fp32 [rows][128], splitting hi|lo on the fly.
__device__ __forceinline__ void fill_f32split(__nv_bfloat16* S, const float* G, int tid) {
    const float4* g = reinterpret_cast<const float4*>(G);  // 32 float4 per row
    for (int i = tid; i < BM * 32; i += 256) {
        int r = i >> 5, c = i & 31;
        float4 v = g[r * 32 + c];
        __nv_bfloat16 h0 = __float2bfloat16(v.x), h1 = __float2bfloat16(v.y);
        __nv_bfloat16 h2 = __float2bfloat16(v.z), h3 = __float2bfloat16(v.w);
        __nv_bfloat162 H0{h0, h1}, H1{h2, h3};
        __nv_bfloat162 L0{__float2bfloat16(v.x - __bfloat162float(h0)),
                          __float2bfloat16(v.y - __bfloat162float(h1))};
        __nv_bfloat162 L1{__float2bfloat16(v.z - __bfloat162float(h2)),
                          __float2bfloat16(v.w - __bfloat162float(h3))};
        __nv_bfloat16* hp = &S[r * LDS_K + c * 4];
        __nv_bfloat16* lp = &S[r * LDS_K + 128 + c * 4];
        *reinterpret_cast<__nv_bfloat162*>(hp)     = H0;
        *reinterpret_cast<__nv_bfloat162*>(hp + 2) = H1;
        *reinterpret_cast<__nv_bfloat162*>(lp)     = L0;
        *reinterpret_cast<__nv_bfloat162*>(lp + 2) = L1;
    }
}

// ---------------------------------------------------------------------------
// Compensated K=384 MMA over [hi|lo] tiles; warp tile 32x32 (mt 2, nt 4).
// Segments (A,B) offsets: (0,0)=hi*hi, (128,0)=lo*hi, (0,128)=hi*lo.
// ---------------------------------------------------------------------------
__device__ __forceinline__ void mma_comp(const __nv_bfloat16* As, const __nv_bfloat16* Bs,
                                         int mrow0, int ncol0, int grp, int tig,
                                         float (&acc)[2][4][4]) {
#pragma unroll
    for (int mt = 0; mt < 2; mt++)
#pragma unroll
        for (int nt = 0; nt < 4; nt++)
#pragma unroll
            for (int q = 0; q < 4; q++) acc[mt][nt][q] = 0.f;

    const int segA[3] = {0, 128, 0};
    const int segB[3] = {0, 0, 128};
#pragma unroll
    for (int seg = 0; seg < 3; seg++) {
#pragma unroll
        for (int ks = 0; ks < 8; ks++) {
            int ka = segA[seg] + ks * 16;
            int kb = segB[seg] + ks * 16;
            uint32_t afr[2][4];
#pragma unroll
            for (int mt = 0; mt < 2; mt++) {
                int r = mrow0 + mt * 16 + grp;
                const uint32_t* p0 = reinterpret_cast<const uint32_t*>(&As[r * LDS_K + ka + tig * 2]);
                const uint32_t* p1 = reinterpret_cast<const uint32_t*>(&As[(r + 8) * LDS_K + ka + tig * 2]);
                afr[mt][0] = p0[0];
                afr[mt][1] = p1[0];
                afr[mt][2] = p0[4];
                afr[mt][3] = p1[4];
            }
            uint32_t bfr[4][2];
#pragma unroll
            for (int nt = 0; nt < 4; nt++) {
                int n = ncol0 + nt * 8 + grp;
                const uint32_t* q = reinterpret_cast<const uint32_t*>(&Bs[n * LDS_K + kb + tig * 2]);
                bfr[nt][0] = q[0];
                bfr[nt][1] = q[4];
            }
#pragma unroll
            for (int mt = 0; mt < 2; mt++)
#pragma unroll
                for (int nt = 0; nt < 4; nt++)
                    asm volatile(
                        "mma.sync.aligned.m16n8k16.row.col.f32.bf16.bf16.f32 "
                        "{%0,%1,%2,%3}, {%4,%5,%6,%7}, {%8,%9}, {%0,%1,%2,%3};"
                        : "+f"(acc[mt][nt][0]), "+f"(acc[mt][nt][1]),
                          "+f"(acc[mt][nt][2]), "+f"(acc[mt][nt][3])
                        : "r"(afr[mt][0]), "r"(afr[mt][1]), "r"(afr[mt][2]), "r"(afr[mt][3]),
                          "r"(bfr[nt][0]), "r"(bfr[nt][1]));
        }
    }
}

// ---------------------------------------------------------------------------
// GEMM: C[M x (nchunks*128)] = A @ W^T (+bias). BM=64, BN=128/chunk.
// 256 thr; warp grid 2(m) x 4(n); warp tile 32x32.
// ---------------------------------------------------------------------------
template <bool F32A>
__global__ void __launch_bounds__(256, 2)
gemm_k(const void* __restrict__ Ap, const __nv_bfloat16* __restrict__ W,
       const float* __restrict__ bias, float* __restrict__ out, int ldc, int nchunks) {
    extern __shared__ __nv_bfloat16 sm[];
    __nv_bfloat16* As = sm;
    __nv_bfloat16* Bs = sm + A_TILE;

    int tid = threadIdx.x;
    int wid = tid >> 5, lane = tid & 31;
    int grp = lane >> 2, tig = lane & 3;
    int mrow0 = (wid & 1) * 32;
    int ncol0 = (wid >> 1) * 32;
    size_t m0 = (size_t)blockIdx.x * BM;

    // B chunk 0 + A via cp.async / manual
    fill_bf16_ca<128>(Bs, W, tid);
    if (F32A) {
        fill_f32split(As, reinterpret_cast<const float*>(Ap) + m0 * 128, tid);
    } else {
        fill_bf16_ca<BM>(As, reinterpret_cast<const __nv_bfloat16*>(Ap) + m0 * 256, tid);
    }
    CP_COMMIT();
    CP_WAIT0();
    __syncthreads();

    for (int j = 0; j < nchunks; j++) {
        float acc[2][4][4];
        mma_comp(As, Bs, mrow0, ncol0, grp, tig, acc);

        int cbase = j * 128;
#pragma unroll
        for (int mt = 0; mt < 2; mt++) {
#pragma unroll
            for (int nt = 0; nt < 4; nt++) {
                size_t row = m0 + mrow0 + mt * 16 + grp;
                int col = cbase + ncol0 + nt * 8 + tig * 2;
                float b0 = 0.f, b1 = 0.f;
                if (bias) { b0 = bias[col]; b1 = bias[col + 1]; }
                float2 v0 = {acc[mt][nt][0] + b0, acc[mt][nt][1] + b1};
                float2 v1 = {acc[mt][nt][2] + b0, acc[mt][nt][3] + b1};
                *reinterpret_cast<float2*>(&out[row * ldc + col]) = v0;
                *reinterpret_cast<float2*>(&out[(row + 8) * ldc + col]) = v1;
            }
        }
        if (j + 1 < nchunks) {
            __syncthreads();   // all MMA reads of Bs done
            fill_bf16_ca<128>(Bs, W + (size_t)(j + 1) * 128 * 256, tid);
            CP_COMMIT();
            CP_WAIT0();
            __syncthreads();
        }
    }
}

// ---------------------------------------------------------------------------
// Fused gh GEMM + GRU gates. A = hidden (fp32, split on the fly), W = w_hh split.
// Same (row,col)->thread map each chunk => r and z gates live in registers.
// ---------------------------------------------------------------------------
__global__ void __launch_bounds__(256, 2)
gemm_gru(const float* __restrict__ hidden, const __nv_bfloat16* __restrict__ W,
         const float* __restrict__ gi, const float* __restrict__ b_hh,
         float* __restrict__ h_out) {
    extern __shared__ __nv_bfloat16 sm[];
    __nv_bfloat16* As = sm;
    __nv_bfloat16* Bs = sm + A_TILE;

    int tid = threadIdx.x;
    int wid = tid >> 5, lane = tid & 31;
    int grp = lane >> 2, tig = lane & 3;
    int mrow0 = (wid & 1) * 32;
    int ncol0 = (wid >> 1) * 32;
    size_t m0 = (size_t)blockIdx.x * BM;

    fill_bf16_ca<128>(Bs, W, tid);
    fill_f32split(As, hidden + m0 * 128, tid);
    CP_COMMIT();
    CP_WAIT0();
    __syncthreads();

    float rreg[2][4][4];
    float zreg[2][4][4];

    for (int j = 0; j < 3; j++) {
        float acc[2][4][4];
        mma_comp(As, Bs, mrow0, ncol0, grp, tig, acc);

#pragma unroll
        for (int mt = 0; mt < 2; mt++) {
#pragma unroll
            for (int nt = 0; nt < 4; nt++) {
                size_t row0 = m0 + mrow0 + mt * 16 + grp;
                int c = ncol0 + nt * 8 + tig * 2;          // hidden dim 0..127
                float bb0 = b_hh[j * 128 + c], bb1 = b_hh[j * 128 + c + 1];
                float2 gi0 = *reinterpret_cast<const float2*>(&gi[row0 * 384 + j * 128 + c]);
                float2 gi1 = *reinterpret_cast<const float2*>(&gi[(row0 + 8) * 384 + j * 128 + c]);
                float gh00 = acc[mt][nt][0] + bb0, gh01 = acc[mt][nt][1] + bb1;
                float gh10 = acc[mt][nt][2] + bb0, gh11 = acc[mt][nt][3] + bb1;
                if (j == 0) {            // r gate
                    rreg[mt][nt][0] = 1.f / (1.f + expf(-(gi0.x + gh00)));
                    rreg[mt][nt][1] = 1.f / (1.f + expf(-(gi0.y + gh01)));
                    rreg[mt][nt][2] = 1.f / (1.f + expf(-(gi1.x + gh10)));
                    rreg[mt][nt][3] = 1.f / (1.f + expf(-(gi1.y + gh11)));
                } else if (j == 1) {     // z gate
                    zreg[mt][nt][0] = 1.f / (1.f + expf(-(gi0.x + gh00)));
                    zreg[mt][nt][1] = 1.f / (1.f + expf(-(gi0.y + gh01)));
                    zreg[mt][nt][2] = 1.f / (1.f + expf(-(gi1.x + gh10)));
                    zreg[mt][nt][3] = 1.f / (1.f + expf(-(gi1.y + gh11)));
                } else {                 // n gate + finalize
                    float n00 = tanhf(gi0.x + rreg[mt][nt][0] * gh00);
                    float n01 = tanhf(gi0.y + rreg[mt][nt][1] * gh01);
                    float n10 = tanhf(gi1.x + rreg[mt][nt][2] * gh10);
                    float n11 = tanhf(gi1.y + rreg[mt][nt][3] * gh11);
                    float2 hv0 = *reinterpret_cast<const float2*>(&hidden[row0 * 128 + c]);
                    float2 hv1 = *reinterpret_cast<const float2*>(&hidden[(row0 + 8) * 128 + c]);
                    float z00 = zreg[mt][nt][0], z01 = zreg[mt][nt][1];
                    float z10 = zreg[mt][nt][2], z11 = zreg[mt][nt][3];
                    float2 o0 = {(1.f - z00) * n00 + z00 * hv0.x,
                                 (1.f - z01) * n01 + z01 * hv0.y};
                    float2 o1 = {(1.f - z10) * n10 + z10 * hv1.x,
                                 (1.f - z11) * n11 + z11 * hv1.y};
                    *reinterpret_cast<float2*>(&h_out[row0 * 128 + c]) = o0;
                    *reinterpret_cast<float2*>(&h_out[(row0 + 8) * 128 + c]) = o1;
                }
            }
        }
        if (j < 2) {
            __syncthreads();
            fill_bf16_ca<128>(Bs, W + (size_t)(j + 1) * 128 * 256, tid);
            CP_COMMIT();
            CP_WAIT0();
            __syncthreads();
        }
    }
}

// ---------------------------------------------------------------------------
// Per-sample: X = relu(normAdj(50x50) @ Y_b(50x128) + b), fused hi|lo split out.
// ---------------------------------------------------------------------------
__global__ void adj_relu_cvt(const float* __restrict__ Y, const float* __restrict__ adj,
                             const float* __restrict__ bias,
                             __nv_bfloat16* __restrict__ outS) {
    __shared__ float A_s[52][52];
    __shared__ float Yb[52][128];
    int b = blockIdx.x, tid = threadIdx.x;

    for (int i = tid; i < 52 * 52; i += 512) {
        int r = i / 52, c = i - r * 52;
        A_s[r][c] = (r < 50 && c < 50) ? adj[r * 50 + c] : 0.f;
    }
    const float* Yg = Y + (size_t)b * 6400;
    for (int i = tid; i < 52 * 128; i += 512) {
        int r = i >> 7, c = i & 127;
        Yb[r][c] = (r < 50) ? Yg[r * 128 + c] : 0.f;
    }
    __syncthreads();

    int g = tid >> 7, d = tid & 127;
    int i0 = g * 13;
    float acc[13];
#pragma unroll
    for (int i = 0; i < 13; i++) acc[i] = 0.f;

#pragma unroll 1
    for (int j = 0; j < 52; j += 4) {
        float y0 = Yb[j + 0][d], y1 = Yb[j + 1][d];
        float y2 = Yb[j + 2][d], y3 = Yb[j + 3][d];
#pragma unroll
        for (int i = 0; i < 13; i++) {
            float4 a = *reinterpret_cast<const float4*>(&A_s[i0 + i][j]);
            acc[i] += a.x * y0 + a.y * y1 + a.z * y2 + a.w * y3;
        }
    }

    float bv = bias[d];
    __nv_bfloat16* os = outS + (size_t)b * 50 * 256;
#pragma unroll
    for (int i = 0; i < 13; i++) {
        int row = i0 + i;
        if (row < 50) {
            float v = fmaxf(acc[i] + bv, 0.f);
            __nv_bfloat16 h = __float2bfloat16(v);
            os[row * 256 + d]       = h;
            os[row * 256 + 128 + d] = __float2bfloat16(v - __bfloat162float(h));
        }
    }
}

// ---------------------------------------------------------------------------
// fp32 [rows][128] -> bf16 [rows][256] (hi|lo), for weights.
// ---------------------------------------------------------------------------
__global__ void cvt_split(const float* __restrict__ in, __nv_bfloat16* __restrict__ outS,
                          int n4) {
    int i = blockIdx.x * blockDim.x + threadIdx.x;
    if (i >= n4) return;
    float4 v = reinterpret_cast<const float4*>(in)[i];
    int row = i >> 5, c4 = (i & 31) << 2;
    __nv_bfloat16 h0 = __float2bfloat16(v.x), h1 = __float2bfloat16(v.y);
    __nv_bfloat16 h2 = __float2bfloat16(v.z), h3 = __float2bfloat16(v.w);
    __nv_bfloat162 H0{h0, h1}, H1{h2, h3};
    __nv_bfloat162 L0{__float2bfloat16(v.x - __bfloat162float(h0)),
                      __float2bfloat16(v.y - __bfloat162float(h1))};
    __nv_bfloat162 L1{__float2bfloat16(v.z - __bfloat162float(h2)),
                      __float2bfloat16(v.w - __bfloat162float(h3))};
    __nv_bfloat16* base = outS + (size_t)row * 256;
    *reinterpret_cast<__nv_bfloat162*>(base + c4)           = H0;
    *reinterpret_cast<__nv_bfloat162*>(base + c4 + 2)       = H1;
    *reinterpret_cast<__nv_bfloat162*>(base + 128 + c4)     = L0;
    *reinterpret_cast<__nv_bfloat162*>(base + 128 + c4 + 2) = L1;
}

// ---------------------------------------------------------------------------
// q[Mx8] = H[Mx128] @ Wfc2[8x128]^T + b[8]
// ---------------------------------------------------------------------------
__global__ void fc2_kernel(const float* __restrict__ H, const float* __restrict__ W,
                           const float* __restrict__ bias, float* __restrict__ Q) {
    __shared__ float Hs[32][132];
    __shared__ float Ws[8][132];
    int tid = threadIdx.x;
    size_t r0 = (size_t)blockIdx.x * 32;

    for (int i = tid; i < 32 * 32; i += 256) {
        int r = i >> 5, c4 = (i & 31) << 2;
        *(float4*)&Hs[r][c4] = *(const float4*)&H[(r0 + r) * 128 + c4];
    }
    for (int i = tid; i < 8 * 32; i += 256) {
        int r = i >> 5, c4 = (i & 31) << 2;
        *(float4*)&Ws[r][c4] = *(const float4*)&W[r * 128 + c4];
    }
    __syncthreads();

    int rl = tid >> 3, a = tid & 7;
    float acc = 0.f;
#pragma unroll
    for (int k = 0; k < 128; k++) acc += Hs[rl][k] * Ws[a][k];
    Q[(r0 + rl) * 8 + a] = acc + bias[a];
}

// ---------------------------------------------------------------------------
extern "C" void kernel_launch(void* const* d_in, const int* in_sizes, int n_in,
                              void* d_out, int out_size) {
    const float* inputs   = (const float*)d_in[0];
    const float* hidden   = (const float*)d_in[1];
    const float* norm_adj = (const float*)d_in[2];
    const float* w_gcn    = (const float*)d_in[3];
    const float* b_gcn    = (const float*)d_in[4];
    const float* w_ih     = (const float*)d_in[5];
    const float* b_ih     = (const float*)d_in[6];
    const float* w_hh     = (const float*)d_in[7];
    const float* b_hh     = (const float*)d_in[8];
    const float* w_fc2    = (const float*)d_in[9];
    const float* b_fc2    = (const float*)d_in[10];

    float* out = (float*)d_out;
    float* q_out = out;               // (102400, 8)
    float* h_out = out + QSIZE;       // (102400, 128)

    float *bufY, *gi;
    __nv_bfloat16 *xs, *wgs, *wihs, *whhs;
    cudaGetSymbolAddress((void**)&bufY, g_bufY);
    cudaGetSymbolAddress((void**)&gi, g_gi);
    cudaGetSymbolAddress((void**)&xs, g_xs);
    cudaGetSymbolAddress((void**)&wgs, g_wgs);
    cudaGetSymbolAddress((void**)&wihs, g_wihs);
    cudaGetSymbolAddress((void**)&whhs, g_whhs);

    cudaFuncSetAttribute(gemm_k<true>,  cudaFuncAttributeMaxDynamicSharedMemorySize, GEMM_SMEM);
    cudaFuncSetAttribute(gemm_k<false>, cudaFuncAttributeMaxDynamicSharedMemorySize, GEMM_SMEM);
    cudaFuncSetAttribute(gemm_gru,      cudaFuncAttributeMaxDynamicSharedMemorySize, GEMM_SMEM);

    // weight conversions (small)
    cvt_split<<<16, 256>>>(w_gcn, wgs, 128 * 128 / 4);
    cvt_split<<<48, 256>>>(w_ih, wihs, 384 * 128 / 4);
    cvt_split<<<48, 256>>>(w_hh, whhs, 384 * 128 / 4);

    const int MT = NROWS / BM;   // 1600 row tiles

    // GCN pass 1: fp32 input, split fused into A fill
    gemm_k<true><<<MT, 256, GEMM_SMEM>>>(inputs, wgs, nullptr, bufY, 128, 1);
    adj_relu_cvt<<<NBATCH, 512>>>(bufY, norm_adj, b_gcn, xs);
    // GCN passes 2,3
    for (int p = 1; p < 3; p++) {
        gemm_k<false><<<MT, 256, GEMM_SMEM>>>(xs, wgs, nullptr, bufY, 128, 1);
        adj_relu_cvt<<<NBATCH, 512>>>(bufY, norm_adj, b_gcn, xs);
    }

    // gi = x_c @ w_ih^T + b_ih
    gemm_k<false><<<MT, 256, GEMM_SMEM>>>(xs, wihs, b_ih, gi, 384, 3);
    // gh gemm fused with GRU gates -> h_out
    gemm_gru<<<MT, 256, GEMM_SMEM>>>(hidden, whhs, gi, b_hh, h_out);

    // fc2 -> q
    fc2_kernel<<<NROWS / 32, 256>>>(h_out, w_fc2, b_fc2, q_out);
}

// round 10
// speedup vs baseline: 1.3850x; 1.1906x over previous
#include <cuda_runtime.h>
#include <cuda_bf16.h>
#include <cstdint>
#include <math.h>

#define NROWS 102400      // BS * N_AGENTS
#define NBATCH 2048
#define QSIZE (NROWS * 8)

// ---------------- static scratch ----------------
// Split layout: row-major [rows][256] bf16, cols 0..127 = hi, 128..255 = lo.
__device__ __nv_bfloat16  g_xs[NROWS * 256];     // GCN output activations, split
__device__ float          g_gi[NROWS * 384];
__device__ __nv_bfloat16  g_wgs[128 * 256];      // w_gcn split
__device__ __nv_bfloat16  g_wihs[384 * 256];     // w_ih split
__device__ __nv_bfloat16  g_whhs[384 * 256];     // w_hh split

// ---------------- tile geometry ----------------
#define LDS_K 264     // K=256 hi|lo + 8 pad
#define BM 64
#define A_TILE (BM * LDS_K)
#define B_TILE (128 * LDS_K)
#define GEMM_SMEM ((A_TILE + B_TILE) * 2)  // 101376 B

// fused GCN smem layout:
//   bf16 Xs [128][264]  @ elem 0
//   bf16 Ws [128][264]  @ elem 33792
//   f32  Yf [2][52][132] @ byte 135168  (52 rows: 2 guard rows, read x0 only)
//   f32  Af [52][52]     @ byte 190080
#define FX_OFF 0
#define FW_OFF (128 * LDS_K)
#define FYF_BYTE (2 * 128 * LDS_K * 2)           // 135168
#define FAF_FLT  (2 * 52 * 132)                  // floats in Yf
#define FUSED_SMEM (FYF_BYTE + (FAF_FLT + 52 * 52) * 4)   // 200896 B

// ---------------- cp.async helpers ----------------
__device__ __forceinline__ uint32_t smem_u32(const void* p) {
    uint32_t a;
    asm("{ .reg .u64 t; cvta.to.shared.u64 t, %1; cvt.u32.u64 %0, t; }" : "=r"(a) : "l"(p));
    return a;
}
#define CP16(dst_u32, src_ptr) \
    asm volatile("cp.async.cg.shared.global [%0], [%1], 16;" :: "r"(dst_u32), "l"(src_ptr))
#define CP_COMMIT()  asm volatile("cp.async.commit_group;" ::: "memory")
#define CP_WAIT0()   asm volatile("cp.async.wait_group 0;" ::: "memory")

template <int ROWS>
__device__ __forceinline__ void fill_bf16_ca(__nv_bfloat16* S, const __nv_bfloat16* G,
                                             int tid) {
    uint32_t sb = smem_u32(S);
    const uint4* g = reinterpret_cast<const uint4*>(G);
    for (int i = tid; i < ROWS * 32; i += 256) {
        int r = i >> 5, c = i & 31;
        CP16(sb + (r * LDS_K + c * 8) * 2, g + r * 32 + c);
    }
}
__device__ __forceinline__ void split_store(__nv_bfloat16* S, int r, int c, float4 v) {
    __nv_bfloat16 h0 = __float2bfloat16(v.x), h1 = __float2bfloat16(v.y);
    __nv_bfloat16 h2 = __float2bfloat16(v.z), h3 = __float2bfloat16(v.w);
    __nv_bfloat162 H0{h0, h1}, H1{h2, h3};
    __nv_bfloat162 L0{__float2bfloat16(v.x - __bfloat162float(h0)),
                      __float2bfloat16(v.y - __bfloat162float(h1))};
    __nv_bfloat162 L1{__float2bfloat16(v.z - __bfloat162float(h2)),
                      __float2bfloat16(v.w - __bfloat162float(h3))};
    __nv_bfloat16* hp = &S[r * LDS_K + c * 4];
    __nv_bfloat16* lp = &S[r * LDS_K + 128 + c * 4];
    *reinterpret_cast<__nv_bfloat162*>(hp)     = H0;
    *reinterpret_cast<__nv_bfloat162*>(hp + 2) = H1;
    *reinterpret_cast<__nv_bfloat162*>(lp)     = L0;
    *reinterpret_cast<__nv_bfloat162*>(lp + 2) = L1;
}
__device__ __forceinline__ void fill_f32split(__nv_bfloat16* S, const float* G, int tid) {
    const float4* g = reinterpret_cast<const float4*>(G);
    for (int i = tid; i < BM * 32; i += 256) {
        int r = i >> 5, c = i & 31;
        split_store(S, r, c, g[r * 32 + c]);
    }
}

// ---------------------------------------------------------------------------
// Compensated MMA over [hi|lo] K=256 tiles (emulates fp32 via 3 bf16 passes).
// Warp tile 32 x (NT*8); MT=2.
// ---------------------------------------------------------------------------
template <int NT>
__device__ __forceinline__ void mma_comp(const __nv_bfloat16* As, const __nv_bfloat16* Bs,
                                         int mrow0, int ncol0, int grp, int tig,
                                         float (&acc)[2][NT][4]) {
#pragma unroll
    for (int mt = 0; mt < 2; mt++)
#pragma unroll
        for (int nt = 0; nt < NT; nt++)
#pragma unroll
            for (int q = 0; q < 4; q++) acc[mt][nt][q] = 0.f;

    const int segA[3] = {0, 128, 0};
    const int segB[3] = {0, 0, 128};
#pragma unroll
    for (int seg = 0; seg < 3; seg++) {
#pragma unroll
        for (int ks = 0; ks < 8; ks++) {
            int ka = segA[seg] + ks * 16;
            int kb = segB[seg] + ks * 16;
            uint32_t afr[2][4];
#pragma unroll
            for (int mt = 0; mt < 2; mt++) {
                int r = mrow0 + mt * 16 + grp;
                const uint32_t* p0 = reinterpret_cast<const uint32_t*>(&As[r * LDS_K + ka + tig * 2]);
                const uint32_t* p1 = reinterpret_cast<const uint32_t*>(&As[(r + 8) * LDS_K + ka + tig * 2]);
                afr[mt][0] = p0[0];
                afr[mt][1] = p1[0];
                afr[mt][2] = p0[4];
                afr[mt][3] = p1[4];
            }
            uint32_t bfr[NT][2];
#pragma unroll
            for (int nt = 0; nt < NT; nt++) {
                int n = ncol0 + nt * 8 + grp;
                const uint32_t* q = reinterpret_cast<const uint32_t*>(&Bs[n * LDS_K + kb + tig * 2]);
                bfr[nt][0] = q[0];
                bfr[nt][1] = q[4];
            }
#pragma unroll
            for (int mt = 0; mt < 2; mt++)
#pragma unroll
                for (int nt = 0; nt < NT; nt++)
                    asm volatile(
                        "mma.sync.aligned.m16n8k16.row.col.f32.bf16.bf16.f32 "
                        "{%0,%1,%2,%3}, {%4,%5,%6,%7}, {%8,%9}, {%0,%1,%2,%3};"
                        : "+f"(acc[mt][nt][0]), "+f"(acc[mt][nt][1]),
                          "+f"(acc[mt][nt][2]), "+f"(acc[mt][nt][3])
                        : "r"(afr[mt][0]), "r"(afr[mt][1]), "r"(afr[mt][2]), "r"(afr[mt][3]),
                          "r"(bfr[nt][0]), "r"(bfr[nt][1]));
        }
    }
}

// ---------------------------------------------------------------------------
// FUSED GCN: one CTA = 2 samples (100 rows, padded to 128). 3 passes of
//   X = relu(adj @ (X @ Wg^T) + b) entirely in smem.
// GEMM on tensor cores (compensated bf16); adj stage in proven fp32 SIMT.
// 256 threads, 1 CTA/SM, grid = NBATCH/2 = 1024.
// ---------------------------------------------------------------------------
__global__ void __launch_bounds__(256, 1)
gcn_fused(const float* __restrict__ inputs, const __nv_bfloat16* __restrict__ Wg,
          const float* __restrict__ norm_adj, const float* __restrict__ b_gcn,
          __nv_bfloat16* __restrict__ xs) {
    extern __shared__ __nv_bfloat16 sm[];
    __nv_bfloat16* Xs = sm + FX_OFF;                                   // [128][264]
    __nv_bfloat16* Ws = sm + FW_OFF;                                   // [128][264]
    float* Yf = reinterpret_cast<float*>(reinterpret_cast<char*>(sm) + FYF_BYTE); // [2*52][132]
    float* Af = Yf + FAF_FLT;                                          // [52][52]

    int tid = threadIdx.x;
    int wid = tid >> 5, lane = tid & 31;
    int grp = lane >> 2, tig = lane & 3;
    // GEMM warp grid: 4(m) x 2(n), warp tile 32x64
    int g_mrow0 = (wid & 3) * 32;
    int g_ncol0 = (wid >> 2) * 64;
    // SIMT adj mapping: thread = (sample, hidden dim)
    int a_s = tid >> 7, a_d = tid & 127;

    size_t m0g = (size_t)blockIdx.x * 100;   // first global row of this CTA

    // --- initial fills ---
    fill_bf16_ca<128>(Ws, Wg, tid);
    {   // X rows 0..99 from inputs (fp32 -> split); rows 100..127 zero
        const float4* g = reinterpret_cast<const float4*>(inputs + m0g * 128);
        for (int i = tid; i < 100 * 32; i += 256) {
            int r = i >> 5, c = i & 31;
            split_store(Xs, r, c, g[r * 32 + c]);
        }
        for (int i = tid; i < 28 * LDS_K / 2; i += 256)
            reinterpret_cast<uint32_t*>(&Xs[100 * LDS_K])[i] = 0;
    }
    {   // adj [52][52], zero-padded
        for (int i = tid; i < 52 * 52; i += 256) {
            int r = i / 52, c = i - r * 52;
            Af[i] = (r < 50 && c < 50) ? norm_adj[r * 50 + c] : 0.f;
        }
    }
    float bv = b_gcn[a_d];
    CP_COMMIT();
    CP_WAIT0();
    __syncthreads();

    for (int p = 0; p < 3; p++) {
        // ---- Y = X @ Wg^T (tensor cores, compensated) -> Yf fp32 ----
        float acc[2][8][4];
        mma_comp<8>(Xs, Ws, g_mrow0, g_ncol0, grp, tig, acc);

#pragma unroll
        for (int mt = 0; mt < 2; mt++) {
#pragma unroll
            for (int half = 0; half < 2; half++) {
                int rr = g_mrow0 + mt * 16 + grp + half * 8;
                if (rr < 100) {
                    int s = (rr >= 50);
                    int j = rr - s * 50;
                    float* yrow = Yf + (s * 52 + j) * 132;
#pragma unroll
                    for (int nt = 0; nt < 8; nt++) {
                        int c = g_ncol0 + nt * 8 + tig * 2;
                        yrow[c]     = acc[mt][nt][half * 2 + 0];
                        yrow[c + 1] = acc[mt][nt][half * 2 + 1];
                    }
                }
            }
        }
        __syncthreads();

        // ---- X' = relu(adj @ Y + b), proven SIMT fp32 pattern ----
        {
            const float* Ys = Yf + a_s * 52 * 132;
            float ac[50];
#pragma unroll
            for (int i = 0; i < 50; i++) ac[i] = 0.f;

#pragma unroll 1
            for (int j = 0; j < 52; j += 4) {
                float y0 = Ys[(j + 0) * 132 + a_d];
                float y1 = Ys[(j + 1) * 132 + a_d];
                float y2 = Ys[(j + 2) * 132 + a_d];
                float y3 = Ys[(j + 3) * 132 + a_d];
#pragma unroll
                for (int i = 0; i < 50; i++) {
                    float4 a = *reinterpret_cast<const float4*>(&Af[i * 52 + j]);
                    ac[i] += a.x * y0 + a.y * y1 + a.z * y2 + a.w * y3;
                }
            }
            if (p < 2) {
#pragma unroll
                for (int i = 0; i < 50; i++) {
                    int row = a_s * 50 + i;
                    float v = fmaxf(ac[i] + bv, 0.f);
                    __nv_bfloat16 h = __float2bfloat16(v);
                    Xs[row * LDS_K + a_d]       = h;
                    Xs[row * LDS_K + 128 + a_d] = __float2bfloat16(v - __bfloat162float(h));
                }
            } else {
#pragma unroll
                for (int i = 0; i < 50; i++) {
                    int row = a_s * 50 + i;
                    float v = fmaxf(ac[i] + bv, 0.f);
                    __nv_bfloat16 h = __float2bfloat16(v);
                    xs[(m0g + row) * 256 + a_d]       = h;
                    xs[(m0g + row) * 256 + 128 + a_d] = __float2bfloat16(v - __bfloat162float(h));
                }
            }
        }
        __syncthreads();
    }
}

// ---------------------------------------------------------------------------
// GEMM: C[M x (nchunks*128)] = A @ W^T (+bias). BM=64, BN=128/chunk.
// 256 thr; warp grid 2(m) x 4(n); warp tile 32x32.  (R8-proven)
// ---------------------------------------------------------------------------
__global__ void __launch_bounds__(256, 2)
gemm_k(const __nv_bfloat16* __restrict__ A, const __nv_bfloat16* __restrict__ W,
       const float* __restrict__ bias, float* __restrict__ out, int ldc, int nchunks) {
    extern __shared__ __nv_bfloat16 sm[];
    __nv_bfloat16* As = sm;
    __nv_bfloat16* Bs = sm + A_TILE;

    int tid = threadIdx.x;
    int wid = tid >> 5, lane = tid & 31;
    int grp = lane >> 2, tig = lane & 3;
    int mrow0 = (wid & 1) * 32;
    int ncol0 = (wid >> 1) * 32;
    size_t m0 = (size_t)blockIdx.x * BM;

    fill_bf16_ca<128>(Bs, W, tid);
    fill_bf16_ca<BM>(As, A + m0 * 256, tid);
    CP_COMMIT();
    CP_WAIT0();
    __syncthreads();

    for (int j = 0; j < nchunks; j++) {
        float acc[2][4][4];
        mma_comp<4>(As, Bs, mrow0, ncol0, grp, tig, acc);

        int cbase = j * 128;
#pragma unroll
        for (int mt = 0; mt < 2; mt++) {
#pragma unroll
            for (int nt = 0; nt < 4; nt++) {
                size_t row = m0 + mrow0 + mt * 16 + grp;
                int col = cbase + ncol0 + nt * 8 + tig * 2;
                float b0 = bias[col], b1 = bias[col + 1];
                float2 v0 = {acc[mt][nt][0] + b0, acc[mt][nt][1] + b1};
                float2 v1 = {acc[mt][nt][2] + b0, acc[mt][nt][3] + b1};
                *reinterpret_cast<float2*>(&out[row * ldc + col]) = v0;
                *reinterpret_cast<float2*>(&out[(row + 8) * ldc + col]) = v1;
            }
        }
        if (j + 1 < nchunks) {
            __syncthreads();
            fill_bf16_ca<128>(Bs, W + (size_t)(j + 1) * 128 * 256, tid);
            CP_COMMIT();
            CP_WAIT0();
            __syncthreads();
        }
    }
}

// ---------------------------------------------------------------------------
// Fused gh GEMM + GRU gates; r and z gates live in registers across chunks.
// (R8-proven)
// ---------------------------------------------------------------------------
__global__ void __launch_bounds__(256, 2)
gemm_gru(const float* __restrict__ hidden, const __nv_bfloat16* __restrict__ W,
         const float* __restrict__ gi, const float* __restrict__ b_hh,
         float* __restrict__ h_out) {
    extern __shared__ __nv_bfloat16 sm[];
    __nv_bfloat16* As = sm;
    __nv_bfloat16* Bs = sm + A_TILE;

    int tid = threadIdx.x;
    int wid = tid >> 5, lane = tid & 31;
    int grp = lane >> 2, tig = lane & 3;
    int mrow0 = (wid & 1) * 32;
    int ncol0 = (wid >> 1) * 32;
    size_t m0 = (size_t)blockIdx.x * BM;

    fill_bf16_ca<128>(Bs, W, tid);
    fill_f32split(As, hidden + m0 * 128, tid);
    CP_COMMIT();
    CP_WAIT0();
    __syncthreads();

    float rreg[2][4][4];
    float zreg[2][4][4];

    for (int j = 0; j < 3; j++) {
        float acc[2][4][4];
        mma_comp<4>(As, Bs, mrow0, ncol0, grp, tig, acc);

#pragma unroll
        for (int mt = 0; mt < 2; mt++) {
#pragma unroll
            for (int nt = 0; nt < 4; nt++) {
                size_t row0 = m0 + mrow0 + mt * 16 + grp;
                int c = ncol0 + nt * 8 + tig * 2;
                float bb0 = b_hh[j * 128 + c], bb1 = b_hh[j * 128 + c + 1];
                float2 gi0 = *reinterpret_cast<const float2*>(&gi[row0 * 384 + j * 128 + c]);
                float2 gi1 = *reinterpret_cast<const float2*>(&gi[(row0 + 8) * 384 + j * 128 + c]);
                float gh00 = acc[mt][nt][0] + bb0, gh01 = acc[mt][nt][1] + bb1;
                float gh10 = acc[mt][nt][2] + bb0, gh11 = acc[mt][nt][3] + bb1;
                if (j == 0) {
                    rreg[mt][nt][0] = 1.f / (1.f + expf(-(gi0.x + gh00)));
                    rreg[mt][nt][1] = 1.f / (1.f + expf(-(gi0.y + gh01)));
                    rreg[mt][nt][2] = 1.f / (1.f + expf(-(gi1.x + gh10)));
                    rreg[mt][nt][3] = 1.f / (1.f + expf(-(gi1.y + gh11)));
                } else if (j == 1) {
                    zreg[mt][nt][0] = 1.f / (1.f + expf(-(gi0.x + gh00)));
                    zreg[mt][nt][1] = 1.f / (1.f + expf(-(gi0.y + gh01)));
                    zreg[mt][nt][2] = 1.f / (1.f + expf(-(gi1.x + gh10)));
                    zreg[mt][nt][3] = 1.f / (1.f + expf(-(gi1.y + gh11)));
                } else {
                    float n00 = tanhf(gi0.x + rreg[mt][nt][0] * gh00);
                    float n01 = tanhf(gi0.y + rreg[mt][nt][1] * gh01);
                    float n10 = tanhf(gi1.x + rreg[mt][nt][2] * gh10);
                    float n11 = tanhf(gi1.y + rreg[mt][nt][3] * gh11);
                    float2 hv0 = *reinterpret_cast<const float2*>(&hidden[row0 * 128 + c]);
                    float2 hv1 = *reinterpret_cast<const float2*>(&hidden[(row0 + 8) * 128 + c]);
                    float z00 = zreg[mt][nt][0], z01 = zreg[mt][nt][1];
                    float z10 = zreg[mt][nt][2], z11 = zreg[mt][nt][3];
                    float2 o0 = {(1.f - z00) * n00 + z00 * hv0.x,
                                 (1.f - z01) * n01 + z01 * hv0.y};
                    float2 o1 = {(1.f - z10) * n10 + z10 * hv1.x,
                                 (1.f - z11) * n11 + z11 * hv1.y};
                    *reinterpret_cast<float2*>(&h_out[row0 * 128 + c]) = o0;
                    *reinterpret_cast<float2*>(&h_out[(row0 + 8) * 128 + c]) = o1;
                }
            }
        }
        if (j < 2) {
            __syncthreads();
            fill_bf16_ca<128>(Bs, W + (size_t)(j + 1) * 128 * 256, tid);
            CP_COMMIT();
            CP_WAIT0();
            __syncthreads();
        }
    }
}

// ---------------------------------------------------------------------------
// fp32 [rows][128] -> bf16 [rows][256] (hi|lo), for weights.
// ---------------------------------------------------------------------------
__global__ void cvt_split(const float* __restrict__ in, __nv_bfloat16* __restrict__ outS,
                          int n4) {
    int i = blockIdx.x * blockDim.x + threadIdx.x;
    if (i >= n4) return;
    float4 v = reinterpret_cast<const float4*>(in)[i];
    int row = i >> 5, c4 = (i & 31) << 2;
    __nv_bfloat16 h0 = __float2bfloat16(v.x), h1 = __float2bfloat16(v.y);
    __nv_bfloat16 h2 = __float2bfloat16(v.z), h3 = __float2bfloat16(v.w);
    __nv_bfloat162 H0{h0, h1}, H1{h2, h3};
    __nv_bfloat162 L0{__float2bfloat16(v.x - __bfloat162float(h0)),
                      __float2bfloat16(v.y - __bfloat162float(h1))};
    __nv_bfloat162 L1{__float2bfloat16(v.z - __bfloat162float(h2)),
                      __float2bfloat16(v.w - __bfloat162float(h3))};
    __nv_bfloat16* base = outS + (size_t)row * 256;
    *reinterpret_cast<__nv_bfloat162*>(base + c4)           = H0;
    *reinterpret_cast<__nv_bfloat162*>(base + c4 + 2)       = H1;
    *reinterpret_cast<__nv_bfloat162*>(base + 128 + c4)     = L0;
    *reinterpret_cast<__nv_bfloat162*>(base + 128 + c4 + 2) = L1;
}

// ---------------------------------------------------------------------------
// q[Mx8] = H[Mx128] @ Wfc2[8x128]^T + b[8]
// ---------------------------------------------------------------------------
__global__ void fc2_kernel(const float* __restrict__ H, const float* __restrict__ W,
                           const float* __restrict__ bias, float* __restrict__ Q) {
    __shared__ float Hs[32][132];
    __shared__ float Ws[8][132];
    int tid = threadIdx.x;
    size_t r0 = (size_t)blockIdx.x * 32;

    for (int i = tid; i < 32 * 32; i += 256) {
        int r = i >> 5, c4 = (i & 31) << 2;
        *(float4*)&Hs[r][c4] = *(const float4*)&H[(r0 + r) * 128 + c4];
    }
    for (int i = tid; i < 8 * 32; i += 256) {
        int r = i >> 5, c4 = (i & 31) << 2;
        *(float4*)&Ws[r][c4] = *(const float4*)&W[r * 128 + c4];
    }
    __syncthreads();

    int rl = tid >> 3, a = tid & 7;
    float acc = 0.f;
#pragma unroll
    for (int k = 0; k < 128; k++) acc += Hs[rl][k] * Ws[a][k];
    Q[(r0 + rl) * 8 + a] = acc + bias[a];
}

// ---------------------------------------------------------------------------
extern "C" void kernel_launch(void* const* d_in, const int* in_sizes, int n_in,
                              void* d_out, int out_size) {
    const float* inputs   = (const float*)d_in[0];
    const float* hidden   = (const float*)d_in[1];
    const float* norm_adj = (const float*)d_in[2];
    const float* w_gcn    = (const float*)d_in[3];
    const float* b_gcn    = (const float*)d_in[4];
    const float* w_ih     = (const float*)d_in[5];
    const float* b_ih     = (const float*)d_in[6];
    const float* w_hh     = (const float*)d_in[7];
    const float* b_hh     = (const float*)d_in[8];
    const float* w_fc2    = (const float*)d_in[9];
    const float* b_fc2    = (const float*)d_in[10];

    float* out = (float*)d_out;
    float* q_out = out;               // (102400, 8)
    float* h_out = out + QSIZE;       // (102400, 128)

    float* gi;
    __nv_bfloat16 *xs, *wgs, *wihs, *whhs;
    cudaGetSymbolAddress((void**)&gi, g_gi);
    cudaGetSymbolAddress((void**)&xs, g_xs);
    cudaGetSymbolAddress((void**)&wgs, g_wgs);
    cudaGetSymbolAddress((void**)&wihs, g_wihs);
    cudaGetSymbolAddress((void**)&whhs, g_whhs);

    cudaFuncSetAttribute(gcn_fused, cudaFuncAttributeMaxDynamicSharedMemorySize, FUSED_SMEM);
    cudaFuncSetAttribute(gemm_k,    cudaFuncAttributeMaxDynamicSharedMemorySize, GEMM_SMEM);
    cudaFuncSetAttribute(gemm_gru,  cudaFuncAttributeMaxDynamicSharedMemorySize, GEMM_SMEM);

    // weight conversions (small)
    cvt_split<<<16, 256>>>(w_gcn, wgs, 128 * 128 / 4);
    cvt_split<<<48, 256>>>(w_ih, wihs, 384 * 128 / 4);
    cvt_split<<<48, 256>>>(w_hh, whhs, 384 * 128 / 4);

    // Fused 3-pass GCN -> xs
    gcn_fused<<<NBATCH / 2, 256, FUSED_SMEM>>>(inputs, wgs, norm_adj, b_gcn, xs);

    // gi = x_c @ w_ih^T + b_ih
    gemm_k<<<NROWS / BM, 256, GEMM_SMEM>>>(xs, wihs, b_ih, gi, 384, 3);
    // gh gemm fused with GRU gates -> h_out
    gemm_gru<<<NROWS / BM, 256, GEMM_SMEM>>>(hidden, whhs, gi, b_hh, h_out);

    // fc2 -> q
    fc2_kernel<<<NROWS / 32, 256>>>(h_out, w_fc2, b_fc2, q_out);
}